// round 5
// baseline (speedup 1.0000x reference)
#include <cuda_runtime.h>
#include <cuda_bf16.h>
#include <cstdint>
#include <cstddef>

// ---------------------------------------------------------------------------
// GIN forward on GB300 — R5
//   CSR-based aggregation (no atomics) + pre-split bf16 activations.
//   h = x @ W_embed ; 3x: z = (1+eps)h + sum_nbr(h); h = MLP(z)
// ---------------------------------------------------------------------------

#define NNODES 100000
#define MPAD   (NNODES + 128)      // row padding for unguarded cp.async tiles
#define EMAX   1700000
#define WTOTAL 172032

__device__ float g_h[(size_t)NNODES * 128];
__device__ __nv_bfloat16 g_zhi[(size_t)MPAD * 128];
__device__ __nv_bfloat16 g_zlo[(size_t)MPAD * 128];
__device__ __nv_bfloat16 g_thi[(size_t)MPAD * 256];
__device__ __nv_bfloat16 g_tlo[(size_t)MPAD * 256];
__device__ int   g_is64;
__device__ __nv_bfloat16 g_whi[WTOTAL];
__device__ __nv_bfloat16 g_wlo[WTOTAL];
// CSR scratch
__device__ int g_deg[NNODES];
__device__ int g_off[NNODES + 1];
__device__ int g_cur[NNODES];
__device__ int g_nbr[EMAX];

// ---------------------------------------------------------------------------
// Edge-index helpers
// ---------------------------------------------------------------------------
__global__ void detect_kernel(const int* __restrict__ p) {
    if (threadIdx.x == 0 && blockIdx.x == 0) {
        int is64 = 1;
        for (int j = 0; j < 128; j++) {
            if (p[2 * j + 1] != 0) { is64 = 0; break; }
        }
        g_is64 = is64;
    }
}

__device__ __forceinline__ int edge_at(const void* p, long long i) {
    return g_is64 ? (int)((const long long*)p)[i] : ((const int*)p)[i];
}

// ---------------------------------------------------------------------------
// CSR build: zero -> hist -> scan -> fill
// ---------------------------------------------------------------------------
__global__ void zero_deg(int n) {
    int i = blockIdx.x * blockDim.x + threadIdx.x;
    if (i < n) g_deg[i] = 0;
}

__global__ void hist_kernel(const void* __restrict__ eidx, int E) {
    int e = blockIdx.x * blockDim.x + threadIdx.x;
    if (e >= E) return;
    atomicAdd(&g_deg[edge_at(eidx, (long long)E + e)], 1);
}

__global__ void scan_kernel(int n) {   // single block, 1024 threads
    __shared__ int part[1024];
    const int t = threadIdx.x;
    const int chunk = (n + 1023) / 1024;
    const int lo = t * chunk;
    const int hi = min(lo + chunk, n);
    int s = 0;
    for (int i = lo; i < hi; i++) s += g_deg[i];
    part[t] = s;
    __syncthreads();
    #pragma unroll
    for (int d = 1; d < 1024; d <<= 1) {
        int v = (t >= d) ? part[t - d] : 0;
        __syncthreads();
        part[t] += v;
        __syncthreads();
    }
    int base = (t > 0) ? part[t - 1] : 0;
    for (int i = lo; i < hi; i++) {
        g_off[i] = base;
        g_cur[i] = base;
        base += g_deg[i];
    }
    if (t == 1023) g_off[n] = base;
}

__global__ void fill_kernel(const void* __restrict__ eidx, int E) {
    int e = blockIdx.x * blockDim.x + threadIdx.x;
    if (e >= E) return;
    int s = edge_at(eidx, e);
    int d = edge_at(eidx, (long long)E + e);
    int pos = atomicAdd(&g_cur[d], 1);
    g_nbr[pos] = s;
}

// ---------------------------------------------------------------------------
// Aggregation: one warp per node. z = (1+eps)*h[i] + sum_{j in nbr(i)} h[j],
// emitted directly as split bf16 (hi/lo).
// ---------------------------------------------------------------------------
__device__ __forceinline__ uint32_t pack_bf16x2(__nv_bfloat16 x, __nv_bfloat16 y) {
    __nv_bfloat162 p = __halves2bfloat162(x, y);
    return *reinterpret_cast<uint32_t*>(&p);
}

__global__ void agg_kernel(const float* __restrict__ h,
                           __nv_bfloat16* __restrict__ zhi,
                           __nv_bfloat16* __restrict__ zlo,
                           const float* __restrict__ eps, int M) {
    int warp = (blockIdx.x * blockDim.x + threadIdx.x) >> 5;
    int lane = threadIdx.x & 31;
    if (warp >= M) return;
    const float4* hp = (const float4*)h;

    float4 acc = hp[(size_t)warp * 32 + lane];
    float se = 1.0f + __ldg(eps);
    acc.x *= se; acc.y *= se; acc.z *= se; acc.w *= se;

    int p   = g_off[warp];
    int end = g_off[warp + 1];
    for (; p + 4 <= end; p += 4) {
        int j0 = g_nbr[p], j1 = g_nbr[p + 1], j2 = g_nbr[p + 2], j3 = g_nbr[p + 3];
        float4 v0 = hp[(size_t)j0 * 32 + lane];
        float4 v1 = hp[(size_t)j1 * 32 + lane];
        float4 v2 = hp[(size_t)j2 * 32 + lane];
        float4 v3 = hp[(size_t)j3 * 32 + lane];
        acc.x += v0.x + v1.x + v2.x + v3.x;
        acc.y += v0.y + v1.y + v2.y + v3.y;
        acc.z += v0.z + v1.z + v2.z + v3.z;
        acc.w += v0.w + v1.w + v2.w + v3.w;
    }
    for (; p < end; p++) {
        float4 v = hp[(size_t)g_nbr[p] * 32 + lane];
        acc.x += v.x; acc.y += v.y; acc.z += v.z; acc.w += v.w;
    }

    __nv_bfloat16 h0 = __float2bfloat16(acc.x), h1 = __float2bfloat16(acc.y);
    __nv_bfloat16 h2 = __float2bfloat16(acc.z), h3 = __float2bfloat16(acc.w);
    __nv_bfloat16 l0 = __float2bfloat16(acc.x - __bfloat162float(h0));
    __nv_bfloat16 l1 = __float2bfloat16(acc.y - __bfloat162float(h1));
    __nv_bfloat16 l2 = __float2bfloat16(acc.z - __bfloat162float(h2));
    __nv_bfloat16 l3 = __float2bfloat16(acc.w - __bfloat162float(h3));
    size_t o = (size_t)warp * 128 + lane * 4;
    *(uint2*)&zhi[o] = make_uint2(pack_bf16x2(h0, h1), pack_bf16x2(h2, h3));
    *(uint2*)&zlo[o] = make_uint2(pack_bf16x2(l0, l1), pack_bf16x2(l2, l3));
}

// ---------------------------------------------------------------------------
// Weight prep (all 7): W[K][N] fp32 -> transposed bf16 hi/lo [N][K]
// ---------------------------------------------------------------------------
struct WSeg { const float* src; int K, N, off; };
struct WAll { WSeg s[7]; };

__global__ void wprep_all(WAll wa, __nv_bfloat16* __restrict__ hi,
                          __nv_bfloat16* __restrict__ lo) {
    int i = blockIdx.x * blockDim.x + threadIdx.x;
    #pragma unroll
    for (int j = 0; j < 7; j++) {
        WSeg sg = wa.s[j];
        int loc = i - sg.off;
        if (loc >= 0 && loc < sg.K * sg.N) {
            int k = loc / sg.N, n = loc % sg.N;
            float x = sg.src[loc];
            __nv_bfloat16 h = __float2bfloat16(x);
            hi[sg.off + n * sg.K + k] = h;
            lo[sg.off + n * sg.K + k] = __float2bfloat16(x - __bfloat162float(h));
        }
    }
}

// ---------------------------------------------------------------------------
// MMA helpers
// ---------------------------------------------------------------------------
__device__ __forceinline__ void mma_bf16(float c[4], const uint32_t a[4],
                                         uint32_t b0, uint32_t b1) {
    asm volatile(
        "mma.sync.aligned.m16n8k16.row.col.f32.bf16.bf16.f32 "
        "{%0,%1,%2,%3}, {%4,%5,%6,%7}, {%8,%9}, {%0,%1,%2,%3};"
        : "+f"(c[0]), "+f"(c[1]), "+f"(c[2]), "+f"(c[3])
        : "r"(a[0]), "r"(a[1]), "r"(a[2]), "r"(a[3]), "r"(b0), "r"(b1));
}

__device__ __forceinline__ void ldsm_x4(uint32_t r[4], uint32_t saddr) {
    asm volatile("ldmatrix.sync.aligned.m8n8.x4.shared.b16 {%0,%1,%2,%3}, [%4];"
                 : "=r"(r[0]), "=r"(r[1]), "=r"(r[2]), "=r"(r[3])
                 : "r"(saddr));
}

__device__ __forceinline__ void cp16(uint32_t saddr, const void* gaddr) {
    asm volatile("cp.async.ca.shared.global [%0], [%1], 16;"
                 :: "r"(saddr), "l"(gaddr) : "memory");
}

// ---------------------------------------------------------------------------
// Tensor-core GEMM. CTA tile 128x128, BK=32, 8 warps (4x2), warp 32x64.
// CONVA: A is fp32 (convert in-tile); else A is pre-split bf16 hi/lo.
// SPLITOUT: write C as bf16 hi/lo pair; else fp32.
// ---------------------------------------------------------------------------
template <int K, int NTOT, bool RELU, bool CONVA, bool SPLITOUT>
__global__ __launch_bounds__(256, 2) void mma_gemm(
    const float* __restrict__ Afp,
    const __nv_bfloat16* __restrict__ Ahi_g,
    const __nv_bfloat16* __restrict__ Alo_g,
    const __nv_bfloat16* __restrict__ Wh,
    const __nv_bfloat16* __restrict__ Wl,
    const float* __restrict__ bias,
    float* __restrict__ C,
    __nv_bfloat16* __restrict__ Chi,
    __nv_bfloat16* __restrict__ Clo,
    int M) {

    __shared__ __nv_bfloat16 Ah[128][40];
    __shared__ __nv_bfloat16 Al[128][40];
    __shared__ __nv_bfloat16 Bh[128][40];
    __shared__ __nv_bfloat16 Bl[128][40];

    const int tid  = threadIdx.x;
    const int lane = tid & 31;
    const int warp = tid >> 5;
    const int wm   = warp >> 1;
    const int wn   = warp & 1;
    const int m0   = blockIdx.x * 128;
    const int n0   = blockIdx.y * 128;
    const int g    = lane >> 2;
    const int q4   = lane & 3;

    const int arow = (lane & 7) + ((lane >> 3) & 1) * 8;
    const int akq  = (lane >> 4) * 8;
    const int bn   = (lane & 7) + ((lane >> 4) & 1) * 8;
    const int bkq  = ((lane >> 3) & 1) * 8;

    uint32_t sAh = (uint32_t)__cvta_generic_to_shared(&Ah[0][0]);
    uint32_t sAl = (uint32_t)__cvta_generic_to_shared(&Al[0][0]);
    uint32_t sBh = (uint32_t)__cvta_generic_to_shared(&Bh[0][0]);
    uint32_t sBl = (uint32_t)__cvta_generic_to_shared(&Bl[0][0]);

    uint32_t aBaseH[2], aBaseL[2], bBaseH[4], bBaseL[4];
    #pragma unroll
    for (int mt = 0; mt < 2; mt++) {
        int r = wm * 32 + mt * 16 + arow;
        aBaseH[mt] = sAh + (uint32_t)(r * 40 + akq) * 2;
        aBaseL[mt] = sAl + (uint32_t)(r * 40 + akq) * 2;
    }
    #pragma unroll
    for (int ntp = 0; ntp < 4; ntp++) {
        int n = wn * 64 + ntp * 16 + bn;
        bBaseH[ntp] = sBh + (uint32_t)(n * 40 + bkq) * 2;
        bBaseL[ntp] = sBl + (uint32_t)(n * 40 + bkq) * 2;
    }

    float acc[2][8][4];
    #pragma unroll
    for (int mt = 0; mt < 2; mt++)
        #pragma unroll
        for (int nt = 0; nt < 8; nt++)
            #pragma unroll
            for (int j = 0; j < 4; j++) acc[mt][nt][j] = 0.0f;

    for (int k0 = 0; k0 < K; k0 += 32) {
        // ---- W tile via cp.async ----
        #pragma unroll
        for (int rep = 0; rep < 2; rep++) {
            int i = tid + rep * 256;
            int n = i >> 2, q = i & 3;
            const size_t off = (size_t)(n0 + n) * K + k0 + q * 8;
            cp16(sBh + (uint32_t)(n * 40 + q * 8) * 2, Wh + off);
            cp16(sBl + (uint32_t)(n * 40 + q * 8) * 2, Wl + off);
        }
        if (CONVA) {
            asm volatile("cp.async.commit_group;");
            // fp32 A -> split bf16 in-tile (embed layer only)
            #pragma unroll
            for (int i = tid; i < 1024; i += 256) {
                int row = i >> 3, kq = i & 7;
                int gr = m0 + row;
                float4 v = make_float4(0.f, 0.f, 0.f, 0.f);
                if (gr < M)
                    v = *(const float4*)(Afp + (size_t)gr * K + k0 + kq * 4);
                __nv_bfloat16 h0 = __float2bfloat16(v.x), h1 = __float2bfloat16(v.y);
                __nv_bfloat16 h2 = __float2bfloat16(v.z), h3 = __float2bfloat16(v.w);
                __nv_bfloat16 l0 = __float2bfloat16(v.x - __bfloat162float(h0));
                __nv_bfloat16 l1 = __float2bfloat16(v.y - __bfloat162float(h1));
                __nv_bfloat16 l2 = __float2bfloat16(v.z - __bfloat162float(h2));
                __nv_bfloat16 l3 = __float2bfloat16(v.w - __bfloat162float(h3));
                *(uint2*)&Ah[row][kq * 4] =
                    make_uint2(pack_bf16x2(h0, h1), pack_bf16x2(h2, h3));
                *(uint2*)&Al[row][kq * 4] =
                    make_uint2(pack_bf16x2(l0, l1), pack_bf16x2(l2, l3));
            }
        } else {
            // pre-split bf16 A tile via cp.async (arrays padded past M)
            #pragma unroll
            for (int rep = 0; rep < 2; rep++) {
                int i = tid + rep * 256;
                int row = i >> 2, q = i & 3;
                const size_t off = (size_t)(m0 + row) * K + k0 + q * 8;
                cp16(sAh + (uint32_t)(row * 40 + q * 8) * 2, Ahi_g + off);
                cp16(sAl + (uint32_t)(row * 40 + q * 8) * 2, Alo_g + off);
            }
            asm volatile("cp.async.commit_group;");
        }
        asm volatile("cp.async.wait_group 0;");
        __syncthreads();

        #pragma unroll
        for (int ks = 0; ks < 32; ks += 16) {
            const uint32_t kofs = (uint32_t)ks * 2;
            uint32_t ah[2][4], al[2][4];
            #pragma unroll
            for (int mt = 0; mt < 2; mt++) {
                ldsm_x4(ah[mt], aBaseH[mt] + kofs);
                ldsm_x4(al[mt], aBaseL[mt] + kofs);
            }
            uint32_t bh[4][4];
            #pragma unroll
            for (int ntp = 0; ntp < 4; ntp++)
                ldsm_x4(bh[ntp], bBaseH[ntp] + kofs);
            #pragma unroll
            for (int nt = 0; nt < 8; nt++) {
                uint32_t b0 = bh[nt >> 1][(nt & 1) * 2];
                uint32_t b1 = bh[nt >> 1][(nt & 1) * 2 + 1];
                #pragma unroll
                for (int mt = 0; mt < 2; mt++) {
                    mma_bf16(acc[mt][nt], ah[mt], b0, b1);
                    mma_bf16(acc[mt][nt], al[mt], b0, b1);
                }
            }
            uint32_t bl[4][4];
            #pragma unroll
            for (int ntp = 0; ntp < 4; ntp++)
                ldsm_x4(bl[ntp], bBaseL[ntp] + kofs);
            #pragma unroll
            for (int nt = 0; nt < 8; nt++) {
                uint32_t b0 = bl[nt >> 1][(nt & 1) * 2];
                uint32_t b1 = bl[nt >> 1][(nt & 1) * 2 + 1];
                #pragma unroll
                for (int mt = 0; mt < 2; mt++)
                    mma_bf16(acc[mt][nt], ah[mt], b0, b1);
            }
        }
        __syncthreads();
    }

    // ---- epilogue ----
    #pragma unroll
    for (int mt = 0; mt < 2; mt++) {
        #pragma unroll
        for (int nt = 0; nt < 8; nt++) {
            int c = n0 + wn * 64 + nt * 8 + 2 * q4;
            float2 bv = make_float2(0.f, 0.f);
            if (bias) bv = *(const float2*)&bias[c];
            int r = m0 + wm * 32 + mt * 16 + g;
            float2 o0, o1;
            o0.x = acc[mt][nt][0] + bv.x;
            o0.y = acc[mt][nt][1] + bv.y;
            o1.x = acc[mt][nt][2] + bv.x;
            o1.y = acc[mt][nt][3] + bv.y;
            if (RELU) {
                o0.x = fmaxf(o0.x, 0.f); o0.y = fmaxf(o0.y, 0.f);
                o1.x = fmaxf(o1.x, 0.f); o1.y = fmaxf(o1.y, 0.f);
            }
            #pragma unroll
            for (int half = 0; half < 2; half++) {
                int rr = r + half * 8;
                float2 o = half ? o1 : o0;
                if (rr < M) {
                    if (SPLITOUT) {
                        __nv_bfloat16 hx = __float2bfloat16(o.x);
                        __nv_bfloat16 hy = __float2bfloat16(o.y);
                        __nv_bfloat16 lx = __float2bfloat16(o.x - __bfloat162float(hx));
                        __nv_bfloat16 ly = __float2bfloat16(o.y - __bfloat162float(hy));
                        *(uint32_t*)&Chi[(size_t)rr * NTOT + c] = pack_bf16x2(hx, hy);
                        *(uint32_t*)&Clo[(size_t)rr * NTOT + c] = pack_bf16x2(lx, ly);
                    } else {
                        *(float2*)&C[(size_t)rr * NTOT + c] = o;
                    }
                }
            }
        }
    }
}

// ---------------------------------------------------------------------------
// Host side
// ---------------------------------------------------------------------------
static __nv_bfloat16 *s_whi, *s_wlo;

template <int K, int NTOT, bool RELU, bool CONVA, bool SPLITOUT>
static void run_gemm(const float* Afp, const __nv_bfloat16* Ahi,
                     const __nv_bfloat16* Alo, int woff, const float* bias,
                     float* C, __nv_bfloat16* Chi, __nv_bfloat16* Clo, int M) {
    dim3 grid((M + 127) / 128, NTOT / 128);
    mma_gemm<K, NTOT, RELU, CONVA, SPLITOUT><<<grid, 256>>>(
        Afp, Ahi, Alo, s_whi + woff, s_wlo + woff, bias, C, Chi, Clo, M);
}

extern "C" void kernel_launch(void* const* d_in, const int* in_sizes, int n_in,
                              void* d_out, int out_size) {
    const float* x       = (const float*)d_in[0];
    const void*  eidx    = d_in[1];
    const float* W_embed = (const float*)d_in[2];
    const float* eps1    = (const float*)d_in[3];
    const float* w1a     = (const float*)d_in[4];
    const float* b1a     = (const float*)d_in[5];
    const float* w1b     = (const float*)d_in[6];
    const float* b1b     = (const float*)d_in[7];
    const float* eps2    = (const float*)d_in[8];
    const float* w2a     = (const float*)d_in[9];
    const float* b2a     = (const float*)d_in[10];
    const float* w2b     = (const float*)d_in[11];
    const float* b2b     = (const float*)d_in[12];
    const float* eps3    = (const float*)d_in[13];
    const float* w3a     = (const float*)d_in[14];
    const float* b3a     = (const float*)d_in[15];
    const float* w3b     = (const float*)d_in[16];
    const float* b3b     = (const float*)d_in[17];

    const int M = in_sizes[0] / 64;
    const int E = in_sizes[1] / 2;

    float* ph;
    __nv_bfloat16 *pzhi, *pzlo, *pthi, *ptlo;
    cudaGetSymbolAddress((void**)&ph,   g_h);
    cudaGetSymbolAddress((void**)&pzhi, g_zhi);
    cudaGetSymbolAddress((void**)&pzlo, g_zlo);
    cudaGetSymbolAddress((void**)&pthi, g_thi);
    cudaGetSymbolAddress((void**)&ptlo, g_tlo);
    cudaGetSymbolAddress((void**)&s_whi, g_whi);
    cudaGetSymbolAddress((void**)&s_wlo, g_wlo);
    float* out = (float*)d_out;

    const int eBlks   = (E + 255) / 256;
    const int aggBlks = (M + 7) / 8;         // 1 warp/node, 8 warps/block

    // ---- CSR build ----
    detect_kernel<<<1, 1>>>((const int*)eidx);
    zero_deg<<<(M + 255) / 256, 256>>>(M);
    hist_kernel<<<eBlks, 256>>>(eidx, E);
    scan_kernel<<<1, 1024>>>(M);
    fill_kernel<<<eBlks, 256>>>(eidx, E);

    // ---- weight prep ----
    WAll wa;
    wa.s[0] = {W_embed,  64, 128, 0};
    wa.s[1] = {w1a, 128, 128, 8192};
    wa.s[2] = {w1b, 128, 128, 24576};
    wa.s[3] = {w2a, 128, 256, 40960};
    wa.s[4] = {w2b, 256, 128, 73728};
    wa.s[5] = {w3a, 128, 256, 106496};
    wa.s[6] = {w3b, 256, 128, 139264};
    wprep_all<<<(WTOTAL + 255) / 256, 256>>>(wa, s_whi, s_wlo);

    // ---- embed: h = x @ W_embed (fp32 in, fp32 out) ----
    run_gemm<64, 128, false, true, false>(x, nullptr, nullptr, 0, nullptr,
                                          ph, nullptr, nullptr, M);

    // ---- conv1 ----
    agg_kernel<<<aggBlks, 256>>>(ph, pzhi, pzlo, eps1, M);
    run_gemm<128, 128, true,  false, true >(nullptr, pzhi, pzlo, 8192,  b1a,
                                            nullptr, pthi, ptlo, M);
    run_gemm<128, 128, false, false, false>(nullptr, pthi, ptlo, 24576, b1b,
                                            ph, nullptr, nullptr, M);

    // ---- conv2 ----
    agg_kernel<<<aggBlks, 256>>>(ph, pzhi, pzlo, eps2, M);
    run_gemm<128, 256, true, false, true >(nullptr, pzhi, pzlo, 40960, b2a,
                                           nullptr, pthi, ptlo, M);
    run_gemm<256, 128, true, false, false>(nullptr, pthi, ptlo, 73728, b2b,
                                           ph, nullptr, nullptr, M);

    // ---- conv3 ----
    agg_kernel<<<aggBlks, 256>>>(ph, pzhi, pzlo, eps3, M);
    run_gemm<128, 256, true, false, true >(nullptr, pzhi, pzlo, 106496, b3a,
                                           nullptr, pthi, ptlo, M);
    run_gemm<256, 128, true, false, false>(nullptr, pthi, ptlo, 139264, b3b,
                                           out, nullptr, nullptr, M);
}

// round 6
// speedup vs baseline: 1.8888x; 1.8888x over previous
#include <cuda_runtime.h>
#include <cuda_bf16.h>
#include <cstdint>
#include <cstddef>

// ---------------------------------------------------------------------------
// GIN forward on GB300 — R6
//   CSR aggregation (no ordered scan: block-atomic segment allocator),
//   pre-split bf16 activations, CSR build overlapped with embed GEMM.
// ---------------------------------------------------------------------------

#define NNODES 100000
#define MPAD   (NNODES + 128)
#define EMAX   1700000
#define WTOTAL 172032

__device__ float g_h[(size_t)NNODES * 128];
__device__ __nv_bfloat16 g_zhi[(size_t)MPAD * 128];
__device__ __nv_bfloat16 g_zlo[(size_t)MPAD * 128];
__device__ __nv_bfloat16 g_thi[(size_t)MPAD * 256];
__device__ __nv_bfloat16 g_tlo[(size_t)MPAD * 256];
__device__ int   g_is64;
__device__ __nv_bfloat16 g_whi[WTOTAL];
__device__ __nv_bfloat16 g_wlo[WTOTAL];
// CSR scratch
__device__ int g_deg[NNODES];
__device__ int g_off[NNODES];     // segment start per node
__device__ int g_cur[NNODES];
__device__ int g_nbr[EMAX];
__device__ int g_alloc;           // segment allocator cursor

// ---------------------------------------------------------------------------
// Edge-index helpers
// ---------------------------------------------------------------------------
__global__ void detect_kernel(const int* __restrict__ p) {
    if (threadIdx.x == 0 && blockIdx.x == 0) {
        int is64 = 1;
        for (int j = 0; j < 128; j++) {
            if (p[2 * j + 1] != 0) { is64 = 0; break; }
        }
        g_is64 = is64;
    }
}

__device__ __forceinline__ int edge_at(const void* p, long long i) {
    return g_is64 ? (int)((const long long*)p)[i] : ((const int*)p)[i];
}

// ---------------------------------------------------------------------------
// CSR build: memset(deg,alloc) -> hist -> offsets(block-atomic) -> fill
// ---------------------------------------------------------------------------
__global__ void hist_kernel(const void* __restrict__ eidx, int E) {
    int e = blockIdx.x * blockDim.x + threadIdx.x;
    if (e >= E) return;
    atomicAdd(&g_deg[edge_at(eidx, (long long)E + e)], 1);
}

// Disjoint-segment allocation: no global ordering needed. Per-block scan of
// degrees + ONE atomicAdd per block on g_alloc.
__global__ void offsets_kernel(int n) {
    const int tid = threadIdx.x;
    const int i = blockIdx.x * 256 + tid;
    const int d = (i < n) ? g_deg[i] : 0;

    // inclusive warp scan
    int x = d;
    #pragma unroll
    for (int o = 1; o < 32; o <<= 1) {
        int v = __shfl_up_sync(0xffffffffu, x, o);
        if ((tid & 31) >= o) x += v;
    }
    __shared__ int wsum[8];
    __shared__ int base;
    if ((tid & 31) == 31) wsum[tid >> 5] = x;
    __syncthreads();
    if (tid < 32) {
        int w = (tid < 8) ? wsum[tid] : 0;
        #pragma unroll
        for (int o = 1; o < 8; o <<= 1) {
            int v = __shfl_up_sync(0xffffffffu, w, o);
            if (tid >= o) w += v;
        }
        if (tid < 8) wsum[tid] = w;                 // inclusive warp totals
        if (tid == 7) base = atomicAdd(&g_alloc, w); // block total
    }
    __syncthreads();
    int excl = x - d + ((tid >= 32) ? wsum[(tid >> 5) - 1] : 0);
    if (i < n) {
        int st = base + excl;
        g_off[i] = st;
        g_cur[i] = st;
    }
}

__global__ void fill_kernel(const void* __restrict__ eidx, int E) {
    int e = blockIdx.x * blockDim.x + threadIdx.x;
    if (e >= E) return;
    int s = edge_at(eidx, e);
    int d = edge_at(eidx, (long long)E + e);
    int pos = atomicAdd(&g_cur[d], 1);
    g_nbr[pos] = s;
}

// ---------------------------------------------------------------------------
// Aggregation: one warp per node. z = (1+eps)*h[i] + sum_{j in nbr(i)} h[j],
// emitted as split bf16 (hi/lo).
// ---------------------------------------------------------------------------
__device__ __forceinline__ uint32_t pack_bf16x2(__nv_bfloat16 x, __nv_bfloat16 y) {
    __nv_bfloat162 p = __halves2bfloat162(x, y);
    return *reinterpret_cast<uint32_t*>(&p);
}

__global__ void agg_kernel(const float* __restrict__ h,
                           __nv_bfloat16* __restrict__ zhi,
                           __nv_bfloat16* __restrict__ zlo,
                           const float* __restrict__ eps, int M) {
    int warp = (blockIdx.x * blockDim.x + threadIdx.x) >> 5;
    int lane = threadIdx.x & 31;
    if (warp >= M) return;
    const float4* hp = (const float4*)h;

    float4 acc = hp[(size_t)warp * 32 + lane];
    float se = 1.0f + __ldg(eps);
    acc.x *= se; acc.y *= se; acc.z *= se; acc.w *= se;

    int p   = g_off[warp];
    int end = p + g_deg[warp];
    for (; p + 4 <= end; p += 4) {
        int j0 = g_nbr[p], j1 = g_nbr[p + 1], j2 = g_nbr[p + 2], j3 = g_nbr[p + 3];
        float4 v0 = hp[(size_t)j0 * 32 + lane];
        float4 v1 = hp[(size_t)j1 * 32 + lane];
        float4 v2 = hp[(size_t)j2 * 32 + lane];
        float4 v3 = hp[(size_t)j3 * 32 + lane];
        acc.x += v0.x + v1.x + v2.x + v3.x;
        acc.y += v0.y + v1.y + v2.y + v3.y;
        acc.z += v0.z + v1.z + v2.z + v3.z;
        acc.w += v0.w + v1.w + v2.w + v3.w;
    }
    for (; p < end; p++) {
        float4 v = hp[(size_t)g_nbr[p] * 32 + lane];
        acc.x += v.x; acc.y += v.y; acc.z += v.z; acc.w += v.w;
    }

    __nv_bfloat16 h0 = __float2bfloat16(acc.x), h1 = __float2bfloat16(acc.y);
    __nv_bfloat16 h2 = __float2bfloat16(acc.z), h3 = __float2bfloat16(acc.w);
    __nv_bfloat16 l0 = __float2bfloat16(acc.x - __bfloat162float(h0));
    __nv_bfloat16 l1 = __float2bfloat16(acc.y - __bfloat162float(h1));
    __nv_bfloat16 l2 = __float2bfloat16(acc.z - __bfloat162float(h2));
    __nv_bfloat16 l3 = __float2bfloat16(acc.w - __bfloat162float(h3));
    size_t o = (size_t)warp * 128 + lane * 4;
    *(uint2*)&zhi[o] = make_uint2(pack_bf16x2(h0, h1), pack_bf16x2(h2, h3));
    *(uint2*)&zlo[o] = make_uint2(pack_bf16x2(l0, l1), pack_bf16x2(l2, l3));
}

// ---------------------------------------------------------------------------
// Weight prep (all 7): W[K][N] fp32 -> transposed bf16 hi/lo [N][K]
// ---------------------------------------------------------------------------
struct WSeg { const float* src; int K, N, off; };
struct WAll { WSeg s[7]; };

__global__ void wprep_all(WAll wa, __nv_bfloat16* __restrict__ hi,
                          __nv_bfloat16* __restrict__ lo) {
    int i = blockIdx.x * blockDim.x + threadIdx.x;
    #pragma unroll
    for (int j = 0; j < 7; j++) {
        WSeg sg = wa.s[j];
        int loc = i - sg.off;
        if (loc >= 0 && loc < sg.K * sg.N) {
            int k = loc / sg.N, n = loc % sg.N;
            float x = sg.src[loc];
            __nv_bfloat16 h = __float2bfloat16(x);
            hi[sg.off + n * sg.K + k] = h;
            lo[sg.off + n * sg.K + k] = __float2bfloat16(x - __bfloat162float(h));
        }
    }
}

// ---------------------------------------------------------------------------
// MMA helpers
// ---------------------------------------------------------------------------
__device__ __forceinline__ void mma_bf16(float c[4], const uint32_t a[4],
                                         uint32_t b0, uint32_t b1) {
    asm volatile(
        "mma.sync.aligned.m16n8k16.row.col.f32.bf16.bf16.f32 "
        "{%0,%1,%2,%3}, {%4,%5,%6,%7}, {%8,%9}, {%0,%1,%2,%3};"
        : "+f"(c[0]), "+f"(c[1]), "+f"(c[2]), "+f"(c[3])
        : "r"(a[0]), "r"(a[1]), "r"(a[2]), "r"(a[3]), "r"(b0), "r"(b1));
}

__device__ __forceinline__ void ldsm_x4(uint32_t r[4], uint32_t saddr) {
    asm volatile("ldmatrix.sync.aligned.m8n8.x4.shared.b16 {%0,%1,%2,%3}, [%4];"
                 : "=r"(r[0]), "=r"(r[1]), "=r"(r[2]), "=r"(r[3])
                 : "r"(saddr));
}

__device__ __forceinline__ void cp16(uint32_t saddr, const void* gaddr) {
    asm volatile("cp.async.ca.shared.global [%0], [%1], 16;"
                 :: "r"(saddr), "l"(gaddr) : "memory");
}

// ---------------------------------------------------------------------------
// Tensor-core GEMM. CTA tile 128x128, BK=32, 8 warps (4x2), warp 32x64.
// CONVA: A fp32, convert in-tile; else pre-split bf16 hi/lo.
// SPLITOUT: C as bf16 hi/lo; else fp32.
// ---------------------------------------------------------------------------
template <int K, int NTOT, bool RELU, bool CONVA, bool SPLITOUT>
__global__ __launch_bounds__(256, 2) void mma_gemm(
    const float* __restrict__ Afp,
    const __nv_bfloat16* __restrict__ Ahi_g,
    const __nv_bfloat16* __restrict__ Alo_g,
    const __nv_bfloat16* __restrict__ Wh,
    const __nv_bfloat16* __restrict__ Wl,
    const float* __restrict__ bias,
    float* __restrict__ C,
    __nv_bfloat16* __restrict__ Chi,
    __nv_bfloat16* __restrict__ Clo,
    int M) {

    __shared__ __nv_bfloat16 Ah[128][40];
    __shared__ __nv_bfloat16 Al[128][40];
    __shared__ __nv_bfloat16 Bh[128][40];
    __shared__ __nv_bfloat16 Bl[128][40];

    const int tid  = threadIdx.x;
    const int lane = tid & 31;
    const int warp = tid >> 5;
    const int wm   = warp >> 1;
    const int wn   = warp & 1;
    const int m0   = blockIdx.x * 128;
    const int n0   = blockIdx.y * 128;
    const int g    = lane >> 2;
    const int q4   = lane & 3;

    const int arow = (lane & 7) + ((lane >> 3) & 1) * 8;
    const int akq  = (lane >> 4) * 8;
    const int bn   = (lane & 7) + ((lane >> 4) & 1) * 8;
    const int bkq  = ((lane >> 3) & 1) * 8;

    uint32_t sAh = (uint32_t)__cvta_generic_to_shared(&Ah[0][0]);
    uint32_t sAl = (uint32_t)__cvta_generic_to_shared(&Al[0][0]);
    uint32_t sBh = (uint32_t)__cvta_generic_to_shared(&Bh[0][0]);
    uint32_t sBl = (uint32_t)__cvta_generic_to_shared(&Bl[0][0]);

    uint32_t aBaseH[2], aBaseL[2], bBaseH[4], bBaseL[4];
    #pragma unroll
    for (int mt = 0; mt < 2; mt++) {
        int r = wm * 32 + mt * 16 + arow;
        aBaseH[mt] = sAh + (uint32_t)(r * 40 + akq) * 2;
        aBaseL[mt] = sAl + (uint32_t)(r * 40 + akq) * 2;
    }
    #pragma unroll
    for (int ntp = 0; ntp < 4; ntp++) {
        int n = wn * 64 + ntp * 16 + bn;
        bBaseH[ntp] = sBh + (uint32_t)(n * 40 + bkq) * 2;
        bBaseL[ntp] = sBl + (uint32_t)(n * 40 + bkq) * 2;
    }

    float acc[2][8][4];
    #pragma unroll
    for (int mt = 0; mt < 2; mt++)
        #pragma unroll
        for (int nt = 0; nt < 8; nt++)
            #pragma unroll
            for (int j = 0; j < 4; j++) acc[mt][nt][j] = 0.0f;

    for (int k0 = 0; k0 < K; k0 += 32) {
        #pragma unroll
        for (int rep = 0; rep < 2; rep++) {
            int i = tid + rep * 256;
            int n = i >> 2, q = i & 3;
            const size_t off = (size_t)(n0 + n) * K + k0 + q * 8;
            cp16(sBh + (uint32_t)(n * 40 + q * 8) * 2, Wh + off);
            cp16(sBl + (uint32_t)(n * 40 + q * 8) * 2, Wl + off);
        }
        if (CONVA) {
            asm volatile("cp.async.commit_group;");
            #pragma unroll
            for (int i = tid; i < 1024; i += 256) {
                int row = i >> 3, kq = i & 7;
                int gr = m0 + row;
                float4 v = make_float4(0.f, 0.f, 0.f, 0.f);
                if (gr < M)
                    v = *(const float4*)(Afp + (size_t)gr * K + k0 + kq * 4);
                __nv_bfloat16 h0 = __float2bfloat16(v.x), h1 = __float2bfloat16(v.y);
                __nv_bfloat16 h2 = __float2bfloat16(v.z), h3 = __float2bfloat16(v.w);
                __nv_bfloat16 l0 = __float2bfloat16(v.x - __bfloat162float(h0));
                __nv_bfloat16 l1 = __float2bfloat16(v.y - __bfloat162float(h1));
                __nv_bfloat16 l2 = __float2bfloat16(v.z - __bfloat162float(h2));
                __nv_bfloat16 l3 = __float2bfloat16(v.w - __bfloat162float(h3));
                *(uint2*)&Ah[row][kq * 4] =
                    make_uint2(pack_bf16x2(h0, h1), pack_bf16x2(h2, h3));
                *(uint2*)&Al[row][kq * 4] =
                    make_uint2(pack_bf16x2(l0, l1), pack_bf16x2(l2, l3));
            }
        } else {
            #pragma unroll
            for (int rep = 0; rep < 2; rep++) {
                int i = tid + rep * 256;
                int row = i >> 2, q = i & 3;
                const size_t off = (size_t)(m0 + row) * K + k0 + q * 8;
                cp16(sAh + (uint32_t)(row * 40 + q * 8) * 2, Ahi_g + off);
                cp16(sAl + (uint32_t)(row * 40 + q * 8) * 2, Alo_g + off);
            }
            asm volatile("cp.async.commit_group;");
        }
        asm volatile("cp.async.wait_group 0;");
        __syncthreads();

        #pragma unroll
        for (int ks = 0; ks < 32; ks += 16) {
            const uint32_t kofs = (uint32_t)ks * 2;
            uint32_t ah[2][4], al[2][4];
            #pragma unroll
            for (int mt = 0; mt < 2; mt++) {
                ldsm_x4(ah[mt], aBaseH[mt] + kofs);
                ldsm_x4(al[mt], aBaseL[mt] + kofs);
            }
            uint32_t bh[4][4];
            #pragma unroll
            for (int ntp = 0; ntp < 4; ntp++)
                ldsm_x4(bh[ntp], bBaseH[ntp] + kofs);
            #pragma unroll
            for (int nt = 0; nt < 8; nt++) {
                uint32_t b0 = bh[nt >> 1][(nt & 1) * 2];
                uint32_t b1 = bh[nt >> 1][(nt & 1) * 2 + 1];
                #pragma unroll
                for (int mt = 0; mt < 2; mt++) {
                    mma_bf16(acc[mt][nt], ah[mt], b0, b1);
                    mma_bf16(acc[mt][nt], al[mt], b0, b1);
                }
            }
            uint32_t bl[4][4];
            #pragma unroll
            for (int ntp = 0; ntp < 4; ntp++)
                ldsm_x4(bl[ntp], bBaseL[ntp] + kofs);
            #pragma unroll
            for (int nt = 0; nt < 8; nt++) {
                uint32_t b0 = bl[nt >> 1][(nt & 1) * 2];
                uint32_t b1 = bl[nt >> 1][(nt & 1) * 2 + 1];
                #pragma unroll
                for (int mt = 0; mt < 2; mt++)
                    mma_bf16(acc[mt][nt], ah[mt], b0, b1);
            }
        }
        __syncthreads();
    }

    #pragma unroll
    for (int mt = 0; mt < 2; mt++) {
        #pragma unroll
        for (int nt = 0; nt < 8; nt++) {
            int c = n0 + wn * 64 + nt * 8 + 2 * q4;
            float2 bv = make_float2(0.f, 0.f);
            if (bias) bv = *(const float2*)&bias[c];
            int r = m0 + wm * 32 + mt * 16 + g;
            float2 o0, o1;
            o0.x = acc[mt][nt][0] + bv.x;
            o0.y = acc[mt][nt][1] + bv.y;
            o1.x = acc[mt][nt][2] + bv.x;
            o1.y = acc[mt][nt][3] + bv.y;
            if (RELU) {
                o0.x = fmaxf(o0.x, 0.f); o0.y = fmaxf(o0.y, 0.f);
                o1.x = fmaxf(o1.x, 0.f); o1.y = fmaxf(o1.y, 0.f);
            }
            #pragma unroll
            for (int half = 0; half < 2; half++) {
                int rr = r + half * 8;
                float2 o = half ? o1 : o0;
                if (rr < M) {
                    if (SPLITOUT) {
                        __nv_bfloat16 hx = __float2bfloat16(o.x);
                        __nv_bfloat16 hy = __float2bfloat16(o.y);
                        __nv_bfloat16 lx = __float2bfloat16(o.x - __bfloat162float(hx));
                        __nv_bfloat16 ly = __float2bfloat16(o.y - __bfloat162float(hy));
                        *(uint32_t*)&Chi[(size_t)rr * NTOT + c] = pack_bf16x2(hx, hy);
                        *(uint32_t*)&Clo[(size_t)rr * NTOT + c] = pack_bf16x2(lx, ly);
                    } else {
                        *(float2*)&C[(size_t)rr * NTOT + c] = o;
                    }
                }
            }
        }
    }
}

// ---------------------------------------------------------------------------
// Host side
// ---------------------------------------------------------------------------
static __nv_bfloat16 *s_whi, *s_wlo;

template <int K, int NTOT, bool RELU, bool CONVA, bool SPLITOUT>
static void run_gemm(const float* Afp, const __nv_bfloat16* Ahi,
                     const __nv_bfloat16* Alo, int woff, const float* bias,
                     float* C, __nv_bfloat16* Chi, __nv_bfloat16* Clo, int M) {
    dim3 grid((M + 127) / 128, NTOT / 128);
    mma_gemm<K, NTOT, RELU, CONVA, SPLITOUT><<<grid, 256>>>(
        Afp, Ahi, Alo, s_whi + woff, s_wlo + woff, bias, C, Chi, Clo, M);
}

extern "C" void kernel_launch(void* const* d_in, const int* in_sizes, int n_in,
                              void* d_out, int out_size) {
    const float* x       = (const float*)d_in[0];
    const void*  eidx    = d_in[1];
    const float* W_embed = (const float*)d_in[2];
    const float* eps1    = (const float*)d_in[3];
    const float* w1a     = (const float*)d_in[4];
    const float* b1a     = (const float*)d_in[5];
    const float* w1b     = (const float*)d_in[6];
    const float* b1b     = (const float*)d_in[7];
    const float* eps2    = (const float*)d_in[8];
    const float* w2a     = (const float*)d_in[9];
    const float* b2a     = (const float*)d_in[10];
    const float* w2b     = (const float*)d_in[11];
    const float* b2b     = (const float*)d_in[12];
    const float* eps3    = (const float*)d_in[13];
    const float* w3a     = (const float*)d_in[14];
    const float* b3a     = (const float*)d_in[15];
    const float* w3b     = (const float*)d_in[16];
    const float* b3b     = (const float*)d_in[17];

    const int M = in_sizes[0] / 64;
    const int E = in_sizes[1] / 2;

    float* ph;
    __nv_bfloat16 *pzhi, *pzlo, *pthi, *ptlo;
    int *pdeg, *palloc;
    cudaGetSymbolAddress((void**)&ph,   g_h);
    cudaGetSymbolAddress((void**)&pzhi, g_zhi);
    cudaGetSymbolAddress((void**)&pzlo, g_zlo);
    cudaGetSymbolAddress((void**)&pthi, g_thi);
    cudaGetSymbolAddress((void**)&ptlo, g_tlo);
    cudaGetSymbolAddress((void**)&s_whi, g_whi);
    cudaGetSymbolAddress((void**)&s_wlo, g_wlo);
    cudaGetSymbolAddress((void**)&pdeg, g_deg);
    cudaGetSymbolAddress((void**)&palloc, g_alloc);
    float* out = (float*)d_out;

    const int eBlks   = (E + 255) / 256;
    const int aggBlks = (M + 7) / 8;

    // ---- side stream + events (lazy init; handles only, no device mem) ----
    static cudaStream_t s1 = nullptr;
    static cudaEvent_t evFork = nullptr, evJoin = nullptr;
    if (!s1) {
        cudaStreamCreateWithFlags(&s1, cudaStreamNonBlocking);
        cudaEventCreateWithFlags(&evFork, cudaEventDisableTiming);
        cudaEventCreateWithFlags(&evJoin, cudaEventDisableTiming);
    }

    // ---- fork: CSR build on s1, weights+embed on main stream ----
    cudaEventRecord(evFork, 0);
    cudaStreamWaitEvent(s1, evFork, 0);

    cudaMemsetAsync(pdeg, 0, (size_t)M * sizeof(int), s1);
    cudaMemsetAsync(palloc, 0, sizeof(int), s1);
    detect_kernel<<<1, 1, 0, s1>>>((const int*)eidx);
    hist_kernel<<<eBlks, 256, 0, s1>>>(eidx, E);
    offsets_kernel<<<(M + 255) / 256, 256, 0, s1>>>(M);
    fill_kernel<<<eBlks, 256, 0, s1>>>(eidx, E);
    cudaEventRecord(evJoin, s1);

    WAll wa;
    wa.s[0] = {W_embed,  64, 128, 0};
    wa.s[1] = {w1a, 128, 128, 8192};
    wa.s[2] = {w1b, 128, 128, 24576};
    wa.s[3] = {w2a, 128, 256, 40960};
    wa.s[4] = {w2b, 256, 128, 73728};
    wa.s[5] = {w3a, 128, 256, 106496};
    wa.s[6] = {w3b, 256, 128, 139264};
    wprep_all<<<(WTOTAL + 255) / 256, 256>>>(wa, s_whi, s_wlo);

    // embed: h = x @ W_embed (fp32 in, fp32 out)
    run_gemm<64, 128, false, true, false>(x, nullptr, nullptr, 0, nullptr,
                                          ph, nullptr, nullptr, M);

    cudaStreamWaitEvent(0, evJoin, 0);   // join before first aggregation

    // ---- conv1 ----
    agg_kernel<<<aggBlks, 256>>>(ph, pzhi, pzlo, eps1, M);
    run_gemm<128, 128, true,  false, true >(nullptr, pzhi, pzlo, 8192,  b1a,
                                            nullptr, pthi, ptlo, M);
    run_gemm<128, 128, false, false, false>(nullptr, pthi, ptlo, 24576, b1b,
                                            ph, nullptr, nullptr, M);

    // ---- conv2 ----
    agg_kernel<<<aggBlks, 256>>>(ph, pzhi, pzlo, eps2, M);
    run_gemm<128, 256, true, false, true >(nullptr, pzhi, pzlo, 40960, b2a,
                                           nullptr, pthi, ptlo, M);
    run_gemm<256, 128, true, false, false>(nullptr, pthi, ptlo, 73728, b2b,
                                           ph, nullptr, nullptr, M);

    // ---- conv3 ----
    agg_kernel<<<aggBlks, 256>>>(ph, pzhi, pzlo, eps3, M);
    run_gemm<128, 256, true, false, true >(nullptr, pzhi, pzlo, 106496, b3a,
                                           nullptr, pthi, ptlo, M);
    run_gemm<256, 128, true, false, false>(nullptr, pthi, ptlo, 139264, b3b,
                                           out, nullptr, nullptr, M);
}

// round 7
// speedup vs baseline: 1.9135x; 1.0131x over previous
#include <cuda_runtime.h>
#include <cuda_bf16.h>
#include <cstdint>
#include <cstddef>

// ---------------------------------------------------------------------------
// GIN forward on GB300 — R7
//   CSR aggregation (block-atomic allocator), pre-split bf16 activations,
//   double-buffered cp.async GEMM pipeline, CSR build overlapped.
// ---------------------------------------------------------------------------

#define NNODES 100000
#define MPAD   (NNODES + 128)
#define EMAX   1700000
#define WTOTAL 172032

__device__ float g_h[(size_t)NNODES * 128];
__device__ __nv_bfloat16 g_zhi[(size_t)MPAD * 128];
__device__ __nv_bfloat16 g_zlo[(size_t)MPAD * 128];
__device__ __nv_bfloat16 g_thi[(size_t)MPAD * 256];
__device__ __nv_bfloat16 g_tlo[(size_t)MPAD * 256];
__device__ int   g_is64;
__device__ __nv_bfloat16 g_whi[WTOTAL];
__device__ __nv_bfloat16 g_wlo[WTOTAL];
// CSR scratch
__device__ int g_deg[NNODES];
__device__ int g_off[NNODES];
__device__ int g_cur[NNODES];
__device__ int g_nbr[EMAX];
__device__ int g_alloc;

// ---------------------------------------------------------------------------
// Edge-index helpers
// ---------------------------------------------------------------------------
__global__ void detect_kernel(const int* __restrict__ p) {
    if (threadIdx.x == 0 && blockIdx.x == 0) {
        int is64 = 1;
        for (int j = 0; j < 128; j++) {
            if (p[2 * j + 1] != 0) { is64 = 0; break; }
        }
        g_is64 = is64;
    }
}

__device__ __forceinline__ int edge_at(const void* p, long long i) {
    return g_is64 ? (int)((const long long*)p)[i] : ((const int*)p)[i];
}

// ---------------------------------------------------------------------------
// CSR build
// ---------------------------------------------------------------------------
__global__ void hist_kernel(const void* __restrict__ eidx, int E) {
    int e = blockIdx.x * blockDim.x + threadIdx.x;
    if (e >= E) return;
    atomicAdd(&g_deg[edge_at(eidx, (long long)E + e)], 1);
}

__global__ void offsets_kernel(int n) {
    const int tid = threadIdx.x;
    const int i = blockIdx.x * 256 + tid;
    const int d = (i < n) ? g_deg[i] : 0;

    int x = d;
    #pragma unroll
    for (int o = 1; o < 32; o <<= 1) {
        int v = __shfl_up_sync(0xffffffffu, x, o);
        if ((tid & 31) >= o) x += v;
    }
    __shared__ int wsum[8];
    __shared__ int base;
    if ((tid & 31) == 31) wsum[tid >> 5] = x;
    __syncthreads();
    if (tid < 32) {
        int w = (tid < 8) ? wsum[tid] : 0;
        #pragma unroll
        for (int o = 1; o < 8; o <<= 1) {
            int v = __shfl_up_sync(0xffffffffu, w, o);
            if (tid >= o) w += v;
        }
        if (tid < 8) wsum[tid] = w;
        if (tid == 7) base = atomicAdd(&g_alloc, w);
    }
    __syncthreads();
    int excl = x - d + ((tid >= 32) ? wsum[(tid >> 5) - 1] : 0);
    if (i < n) {
        int st = base + excl;
        g_off[i] = st;
        g_cur[i] = st;
    }
}

__global__ void fill_kernel(const void* __restrict__ eidx, int E) {
    int e = blockIdx.x * blockDim.x + threadIdx.x;
    if (e >= E) return;
    int s = edge_at(eidx, e);
    int d = edge_at(eidx, (long long)E + e);
    int pos = atomicAdd(&g_cur[d], 1);
    g_nbr[pos] = s;
}

// ---------------------------------------------------------------------------
// Aggregation: one warp per node. z = (1+eps)*h[i] + sum_nbr h[j], split bf16.
// ---------------------------------------------------------------------------
__device__ __forceinline__ uint32_t pack_bf16x2(__nv_bfloat16 x, __nv_bfloat16 y) {
    __nv_bfloat162 p = __halves2bfloat162(x, y);
    return *reinterpret_cast<uint32_t*>(&p);
}

__global__ void agg_kernel(const float* __restrict__ h,
                           __nv_bfloat16* __restrict__ zhi,
                           __nv_bfloat16* __restrict__ zlo,
                           const float* __restrict__ eps, int M) {
    int warp = (blockIdx.x * blockDim.x + threadIdx.x) >> 5;
    int lane = threadIdx.x & 31;
    if (warp >= M) return;
    const float4* hp = (const float4*)h;

    float4 acc = hp[(size_t)warp * 32 + lane];
    float se = 1.0f + __ldg(eps);
    acc.x *= se; acc.y *= se; acc.z *= se; acc.w *= se;

    int p   = g_off[warp];
    int end = p + g_deg[warp];
    for (; p + 4 <= end; p += 4) {
        int j0 = g_nbr[p], j1 = g_nbr[p + 1], j2 = g_nbr[p + 2], j3 = g_nbr[p + 3];
        float4 v0 = hp[(size_t)j0 * 32 + lane];
        float4 v1 = hp[(size_t)j1 * 32 + lane];
        float4 v2 = hp[(size_t)j2 * 32 + lane];
        float4 v3 = hp[(size_t)j3 * 32 + lane];
        acc.x += v0.x + v1.x + v2.x + v3.x;
        acc.y += v0.y + v1.y + v2.y + v3.y;
        acc.z += v0.z + v1.z + v2.z + v3.z;
        acc.w += v0.w + v1.w + v2.w + v3.w;
    }
    for (; p < end; p++) {
        float4 v = hp[(size_t)g_nbr[p] * 32 + lane];
        acc.x += v.x; acc.y += v.y; acc.z += v.z; acc.w += v.w;
    }

    __nv_bfloat16 h0 = __float2bfloat16(acc.x), h1 = __float2bfloat16(acc.y);
    __nv_bfloat16 h2 = __float2bfloat16(acc.z), h3 = __float2bfloat16(acc.w);
    __nv_bfloat16 l0 = __float2bfloat16(acc.x - __bfloat162float(h0));
    __nv_bfloat16 l1 = __float2bfloat16(acc.y - __bfloat162float(h1));
    __nv_bfloat16 l2 = __float2bfloat16(acc.z - __bfloat162float(h2));
    __nv_bfloat16 l3 = __float2bfloat16(acc.w - __bfloat162float(h3));
    size_t o = (size_t)warp * 128 + lane * 4;
    *(uint2*)&zhi[o] = make_uint2(pack_bf16x2(h0, h1), pack_bf16x2(h2, h3));
    *(uint2*)&zlo[o] = make_uint2(pack_bf16x2(l0, l1), pack_bf16x2(l2, l3));
}

// ---------------------------------------------------------------------------
// Weight prep (all 7): W[K][N] fp32 -> transposed bf16 hi/lo [N][K]
// ---------------------------------------------------------------------------
struct WSeg { const float* src; int K, N, off; };
struct WAll { WSeg s[7]; };

__global__ void wprep_all(WAll wa, __nv_bfloat16* __restrict__ hi,
                          __nv_bfloat16* __restrict__ lo) {
    int i = blockIdx.x * blockDim.x + threadIdx.x;
    #pragma unroll
    for (int j = 0; j < 7; j++) {
        WSeg sg = wa.s[j];
        int loc = i - sg.off;
        if (loc >= 0 && loc < sg.K * sg.N) {
            int k = loc / sg.N, n = loc % sg.N;
            float x = sg.src[loc];
            __nv_bfloat16 h = __float2bfloat16(x);
            hi[sg.off + n * sg.K + k] = h;
            lo[sg.off + n * sg.K + k] = __float2bfloat16(x - __bfloat162float(h));
        }
    }
}

// x [M,64] fp32 -> split bf16 (same layout)
__global__ void xprep_kernel(const float* __restrict__ x,
                             __nv_bfloat16* __restrict__ hi,
                             __nv_bfloat16* __restrict__ lo, int n) {
    int i = blockIdx.x * blockDim.x + threadIdx.x;
    if (i >= n) return;
    float v = x[i];
    __nv_bfloat16 h = __float2bfloat16(v);
    hi[i] = h;
    lo[i] = __float2bfloat16(v - __bfloat162float(h));
}

// ---------------------------------------------------------------------------
// MMA helpers
// ---------------------------------------------------------------------------
__device__ __forceinline__ void mma_bf16(float c[4], const uint32_t a[4],
                                         uint32_t b0, uint32_t b1) {
    asm volatile(
        "mma.sync.aligned.m16n8k16.row.col.f32.bf16.bf16.f32 "
        "{%0,%1,%2,%3}, {%4,%5,%6,%7}, {%8,%9}, {%0,%1,%2,%3};"
        : "+f"(c[0]), "+f"(c[1]), "+f"(c[2]), "+f"(c[3])
        : "r"(a[0]), "r"(a[1]), "r"(a[2]), "r"(a[3]), "r"(b0), "r"(b1));
}

__device__ __forceinline__ void ldsm_x4(uint32_t r[4], uint32_t saddr) {
    asm volatile("ldmatrix.sync.aligned.m8n8.x4.shared.b16 {%0,%1,%2,%3}, [%4];"
                 : "=r"(r[0]), "=r"(r[1]), "=r"(r[2]), "=r"(r[3])
                 : "r"(saddr));
}

__device__ __forceinline__ void cp16(uint32_t saddr, const void* gaddr) {
    asm volatile("cp.async.ca.shared.global [%0], [%1], 16;"
                 :: "r"(saddr), "l"(gaddr) : "memory");
}

// ---------------------------------------------------------------------------
// Double-buffered tensor-core GEMM. CTA tile 128x128, BK=32, 8 warps (4x2).
// A pre-split bf16 hi/lo; 3-term product. Dynamic smem: 2 stages x 40960B.
// ---------------------------------------------------------------------------
#define STG_ELEM  5120                     // 128*40 bf16 per array
#define STG_BYTES (4 * STG_ELEM * 2)       // 40960 bytes per stage

template <int K, int NTOT, bool RELU, bool SPLITOUT>
__global__ __launch_bounds__(256, 2) void mma_gemm(
    const __nv_bfloat16* __restrict__ Ahi_g,
    const __nv_bfloat16* __restrict__ Alo_g,
    const __nv_bfloat16* __restrict__ Wh,
    const __nv_bfloat16* __restrict__ Wl,
    const float* __restrict__ bias,
    float* __restrict__ C,
    __nv_bfloat16* __restrict__ Chi,
    __nv_bfloat16* __restrict__ Clo,
    int M) {

    extern __shared__ __nv_bfloat16 smem[];
    const uint32_t sbase = (uint32_t)__cvta_generic_to_shared(smem);

    const int tid  = threadIdx.x;
    const int lane = tid & 31;
    const int warp = tid >> 5;
    const int wm   = warp >> 1;
    const int wn   = warp & 1;
    const int m0   = blockIdx.x * 128;
    const int n0   = blockIdx.y * 128;
    const int g    = lane >> 2;
    const int q4   = lane & 3;

    const int arow = (lane & 7) + ((lane >> 3) & 1) * 8;
    const int akq  = (lane >> 4) * 8;
    const int bn   = (lane & 7) + ((lane >> 4) & 1) * 8;
    const int bkq  = ((lane >> 3) & 1) * 8;

    // fragment base addresses relative to stage 0
    uint32_t aBaseH[2], bBaseH[4];
    #pragma unroll
    for (int mt = 0; mt < 2; mt++) {
        int r = wm * 32 + mt * 16 + arow;
        aBaseH[mt] = sbase + (uint32_t)(r * 40 + akq) * 2;
    }
    #pragma unroll
    for (int ntp = 0; ntp < 4; ntp++) {
        int n = wn * 64 + ntp * 16 + bn;
        bBaseH[ntp] = sbase + (uint32_t)(2 * STG_ELEM + n * 40 + bkq) * 2;
    }

    // tile issue: A rows + B rows share the same 128x(32k) mapping
    auto issue_tile = [&](int s, int k0) {
        uint32_t b = sbase + (uint32_t)s * STG_BYTES;
        #pragma unroll
        for (int rep = 0; rep < 2; rep++) {
            int i = tid + rep * 256;
            int row = i >> 2, q = i & 3;
            uint32_t so = (uint32_t)(row * 40 + q * 8) * 2;
            size_t ga = (size_t)(m0 + row) * K + k0 + q * 8;
            size_t gb = (size_t)(n0 + row) * K + k0 + q * 8;
            cp16(b + so, Ahi_g + ga);
            cp16(b + STG_ELEM * 2 + so, Alo_g + ga);
            cp16(b + 2 * STG_ELEM * 2 + so, Wh + gb);
            cp16(b + 3 * STG_ELEM * 2 + so, Wl + gb);
        }
        asm volatile("cp.async.commit_group;");
    };

    float acc[2][8][4];
    #pragma unroll
    for (int mt = 0; mt < 2; mt++)
        #pragma unroll
        for (int nt = 0; nt < 8; nt++)
            #pragma unroll
            for (int j = 0; j < 4; j++) acc[mt][nt][j] = 0.0f;

    constexpr int NIT = K / 32;
    issue_tile(0, 0);

    #pragma unroll
    for (int it = 0; it < NIT; it++) {
        if (it + 1 < NIT) {
            issue_tile((it + 1) & 1, (it + 1) * 32);
            asm volatile("cp.async.wait_group 1;");
        } else {
            asm volatile("cp.async.wait_group 0;");
        }
        __syncthreads();

        const uint32_t st = (uint32_t)(it & 1) * STG_BYTES;
        #pragma unroll
        for (int ks = 0; ks < 32; ks += 16) {
            const uint32_t kofs = st + (uint32_t)ks * 2;
            uint32_t ah[2][4], al[2][4];
            #pragma unroll
            for (int mt = 0; mt < 2; mt++) {
                ldsm_x4(ah[mt], aBaseH[mt] + kofs);
                ldsm_x4(al[mt], aBaseH[mt] + STG_ELEM * 2 + kofs);
            }
            uint32_t bh[4][4];
            #pragma unroll
            for (int ntp = 0; ntp < 4; ntp++)
                ldsm_x4(bh[ntp], bBaseH[ntp] + kofs);
            #pragma unroll
            for (int nt = 0; nt < 8; nt++) {
                uint32_t b0 = bh[nt >> 1][(nt & 1) * 2];
                uint32_t b1 = bh[nt >> 1][(nt & 1) * 2 + 1];
                #pragma unroll
                for (int mt = 0; mt < 2; mt++) {
                    mma_bf16(acc[mt][nt], ah[mt], b0, b1);
                    mma_bf16(acc[mt][nt], al[mt], b0, b1);
                }
            }
            uint32_t bl[4][4];
            #pragma unroll
            for (int ntp = 0; ntp < 4; ntp++)
                ldsm_x4(bl[ntp], bBaseH[ntp] + STG_ELEM * 2 + kofs);
            #pragma unroll
            for (int nt = 0; nt < 8; nt++) {
                uint32_t b0 = bl[nt >> 1][(nt & 1) * 2];
                uint32_t b1 = bl[nt >> 1][(nt & 1) * 2 + 1];
                #pragma unroll
                for (int mt = 0; mt < 2; mt++)
                    mma_bf16(acc[mt][nt], ah[mt], b0, b1);
            }
        }
        __syncthreads();
    }

    // ---- epilogue ----
    #pragma unroll
    for (int mt = 0; mt < 2; mt++) {
        #pragma unroll
        for (int nt = 0; nt < 8; nt++) {
            int c = n0 + wn * 64 + nt * 8 + 2 * q4;
            float2 bv = make_float2(0.f, 0.f);
            if (bias) bv = *(const float2*)&bias[c];
            int r = m0 + wm * 32 + mt * 16 + g;
            float2 o0, o1;
            o0.x = acc[mt][nt][0] + bv.x;
            o0.y = acc[mt][nt][1] + bv.y;
            o1.x = acc[mt][nt][2] + bv.x;
            o1.y = acc[mt][nt][3] + bv.y;
            if (RELU) {
                o0.x = fmaxf(o0.x, 0.f); o0.y = fmaxf(o0.y, 0.f);
                o1.x = fmaxf(o1.x, 0.f); o1.y = fmaxf(o1.y, 0.f);
            }
            #pragma unroll
            for (int half = 0; half < 2; half++) {
                int rr = r + half * 8;
                float2 o = half ? o1 : o0;
                if (rr < M) {
                    if (SPLITOUT) {
                        __nv_bfloat16 hx = __float2bfloat16(o.x);
                        __nv_bfloat16 hy = __float2bfloat16(o.y);
                        __nv_bfloat16 lx = __float2bfloat16(o.x - __bfloat162float(hx));
                        __nv_bfloat16 ly = __float2bfloat16(o.y - __bfloat162float(hy));
                        *(uint32_t*)&Chi[(size_t)rr * NTOT + c] = pack_bf16x2(hx, hy);
                        *(uint32_t*)&Clo[(size_t)rr * NTOT + c] = pack_bf16x2(lx, ly);
                    } else {
                        *(float2*)&C[(size_t)rr * NTOT + c] = o;
                    }
                }
            }
        }
    }
}

// ---------------------------------------------------------------------------
// Host side
// ---------------------------------------------------------------------------
static __nv_bfloat16 *s_whi, *s_wlo;

template <int K, int NTOT, bool RELU, bool SPLITOUT>
static void run_gemm(const __nv_bfloat16* Ahi, const __nv_bfloat16* Alo,
                     int woff, const float* bias,
                     float* C, __nv_bfloat16* Chi, __nv_bfloat16* Clo, int M) {
    cudaFuncSetAttribute(mma_gemm<K, NTOT, RELU, SPLITOUT>,
                         cudaFuncAttributeMaxDynamicSharedMemorySize,
                         2 * STG_BYTES);
    dim3 grid((M + 127) / 128, NTOT / 128);
    mma_gemm<K, NTOT, RELU, SPLITOUT><<<grid, 256, 2 * STG_BYTES>>>(
        Ahi, Alo, s_whi + woff, s_wlo + woff, bias, C, Chi, Clo, M);
}

extern "C" void kernel_launch(void* const* d_in, const int* in_sizes, int n_in,
                              void* d_out, int out_size) {
    const float* x       = (const float*)d_in[0];
    const void*  eidx    = d_in[1];
    const float* W_embed = (const float*)d_in[2];
    const float* eps1    = (const float*)d_in[3];
    const float* w1a     = (const float*)d_in[4];
    const float* b1a     = (const float*)d_in[5];
    const float* w1b     = (const float*)d_in[6];
    const float* b1b     = (const float*)d_in[7];
    const float* eps2    = (const float*)d_in[8];
    const float* w2a     = (const float*)d_in[9];
    const float* b2a     = (const float*)d_in[10];
    const float* w2b     = (const float*)d_in[11];
    const float* b2b     = (const float*)d_in[12];
    const float* eps3    = (const float*)d_in[13];
    const float* w3a     = (const float*)d_in[14];
    const float* b3a     = (const float*)d_in[15];
    const float* w3b     = (const float*)d_in[16];
    const float* b3b     = (const float*)d_in[17];

    const int M = in_sizes[0] / 64;
    const int E = in_sizes[1] / 2;

    float* ph;
    __nv_bfloat16 *pzhi, *pzlo, *pthi, *ptlo;
    int *pdeg, *palloc;
    cudaGetSymbolAddress((void**)&ph,   g_h);
    cudaGetSymbolAddress((void**)&pzhi, g_zhi);
    cudaGetSymbolAddress((void**)&pzlo, g_zlo);
    cudaGetSymbolAddress((void**)&pthi, g_thi);
    cudaGetSymbolAddress((void**)&ptlo, g_tlo);
    cudaGetSymbolAddress((void**)&s_whi, g_whi);
    cudaGetSymbolAddress((void**)&s_wlo, g_wlo);
    cudaGetSymbolAddress((void**)&pdeg, g_deg);
    cudaGetSymbolAddress((void**)&palloc, g_alloc);
    float* out = (float*)d_out;

    const int eBlks   = (E + 255) / 256;
    const int aggBlks = (M + 7) / 8;

    static cudaStream_t s1 = nullptr;
    static cudaEvent_t evFork = nullptr, evJoin = nullptr;
    if (!s1) {
        cudaStreamCreateWithFlags(&s1, cudaStreamNonBlocking);
        cudaEventCreateWithFlags(&evFork, cudaEventDisableTiming);
        cudaEventCreateWithFlags(&evJoin, cudaEventDisableTiming);
    }

    // ---- fork: CSR build on s1 ----
    cudaEventRecord(evFork, 0);
    cudaStreamWaitEvent(s1, evFork, 0);

    cudaMemsetAsync(pdeg, 0, (size_t)M * sizeof(int), s1);
    cudaMemsetAsync(palloc, 0, sizeof(int), s1);
    detect_kernel<<<1, 1, 0, s1>>>((const int*)eidx);
    hist_kernel<<<eBlks, 256, 0, s1>>>(eidx, E);
    offsets_kernel<<<(M + 255) / 256, 256, 0, s1>>>(M);
    fill_kernel<<<eBlks, 256, 0, s1>>>(eidx, E);
    cudaEventRecord(evJoin, s1);

    // ---- main stream: weights + x split + embed ----
    WAll wa;
    wa.s[0] = {W_embed,  64, 128, 0};
    wa.s[1] = {w1a, 128, 128, 8192};
    wa.s[2] = {w1b, 128, 128, 24576};
    wa.s[3] = {w2a, 128, 256, 40960};
    wa.s[4] = {w2b, 256, 128, 73728};
    wa.s[5] = {w3a, 128, 256, 106496};
    wa.s[6] = {w3b, 256, 128, 139264};
    wprep_all<<<(WTOTAL + 255) / 256, 256>>>(wa, s_whi, s_wlo);

    // x -> split bf16 into t-buffers (free until conv1's first GEMM)
    xprep_kernel<<<(M * 64 + 255) / 256, 256>>>(x, pthi, ptlo, M * 64);

    // embed: h = x @ W_embed
    run_gemm<64, 128, false, false>(pthi, ptlo, 0, nullptr,
                                    ph, nullptr, nullptr, M);

    cudaStreamWaitEvent(0, evJoin, 0);

    // ---- conv1 ----
    agg_kernel<<<aggBlks, 256>>>(ph, pzhi, pzlo, eps1, M);
    run_gemm<128, 128, true,  true >(pzhi, pzlo, 8192,  b1a,
                                     nullptr, pthi, ptlo, M);
    run_gemm<128, 128, false, false>(pthi, ptlo, 24576, b1b,
                                     ph, nullptr, nullptr, M);

    // ---- conv2 ----
    agg_kernel<<<aggBlks, 256>>>(ph, pzhi, pzlo, eps2, M);
    run_gemm<128, 256, true, true >(pzhi, pzlo, 40960, b2a,
                                    nullptr, pthi, ptlo, M);
    run_gemm<256, 128, true, false>(pthi, ptlo, 73728, b2b,
                                    ph, nullptr, nullptr, M);

    // ---- conv3 ----
    agg_kernel<<<aggBlks, 256>>>(ph, pzhi, pzlo, eps3, M);
    run_gemm<128, 256, true, true >(pzhi, pzlo, 106496, b3a,
                                    nullptr, pthi, ptlo, M);
    run_gemm<256, 128, true, false>(pthi, ptlo, 139264, b3b,
                                    out, nullptr, nullptr, M);
}

// round 10
// speedup vs baseline: 2.1390x; 1.1179x over previous
#include <cuda_runtime.h>
#include <cuda_fp16.h>
#include <cstdint>
#include <cstddef>

// ---------------------------------------------------------------------------
// GIN forward on GB300 — R9
//   CSR aggregation (block-atomic allocator), pre-split fp16 activations,
//   2-term fp16 GEMMs ((Ah+Al) @ Wh == fp32 acts x fp16 weights),
//   double-buffered cp.async pipeline, CSR build overlapped.
// ---------------------------------------------------------------------------

#define NNODES 100000
#define MPAD   (NNODES + 128)
#define EMAX   1700000
#define WTOTAL 172032

__device__ float g_h[(size_t)NNODES * 128];
__device__ __half g_zhi[(size_t)MPAD * 128];
__device__ __half g_zlo[(size_t)MPAD * 128];
__device__ __half g_thi[(size_t)MPAD * 256];
__device__ __half g_tlo[(size_t)MPAD * 256];
__device__ int    g_is64;
__device__ __half g_whi[WTOTAL];
// CSR scratch
__device__ int g_deg[NNODES];
__device__ int g_off[NNODES];
__device__ int g_cur[NNODES];
__device__ int g_nbr[EMAX];
__device__ int g_alloc;

// ---------------------------------------------------------------------------
// Edge-index helpers
// ---------------------------------------------------------------------------
__global__ void detect_kernel(const int* __restrict__ p) {
    if (threadIdx.x == 0 && blockIdx.x == 0) {
        int is64 = 1;
        for (int j = 0; j < 128; j++) {
            if (p[2 * j + 1] != 0) { is64 = 0; break; }
        }
        g_is64 = is64;
    }
}

__device__ __forceinline__ int edge_at(const void* p, long long i) {
    return g_is64 ? (int)((const long long*)p)[i] : ((const int*)p)[i];
}

// ---------------------------------------------------------------------------
// CSR build
// ---------------------------------------------------------------------------
__global__ void hist_kernel(const void* __restrict__ eidx, int E) {
    int e = blockIdx.x * blockDim.x + threadIdx.x;
    if (e >= E) return;
    atomicAdd(&g_deg[edge_at(eidx, (long long)E + e)], 1);
}

__global__ void offsets_kernel(int n) {
    const int tid = threadIdx.x;
    const int i = blockIdx.x * 256 + tid;
    const int d = (i < n) ? g_deg[i] : 0;

    int x = d;
    #pragma unroll
    for (int o = 1; o < 32; o <<= 1) {
        int v = __shfl_up_sync(0xffffffffu, x, o);
        if ((tid & 31) >= o) x += v;
    }
    __shared__ int wsum[8];
    __shared__ int base;
    if ((tid & 31) == 31) wsum[tid >> 5] = x;
    __syncthreads();
    if (tid < 32) {
        int w = (tid < 8) ? wsum[tid] : 0;
        #pragma unroll
        for (int o = 1; o < 8; o <<= 1) {
            int v = __shfl_up_sync(0xffffffffu, w, o);
            if (tid >= o) w += v;
        }
        if (tid < 8) wsum[tid] = w;
        if (tid == 7) base = atomicAdd(&g_alloc, w);
    }
    __syncthreads();
    int excl = x - d + ((tid >= 32) ? wsum[(tid >> 5) - 1] : 0);
    if (i < n) {
        int st = base + excl;
        g_off[i] = st;
        g_cur[i] = st;
    }
}

__global__ void fill_kernel(const void* __restrict__ eidx, int E) {
    int e = blockIdx.x * blockDim.x + threadIdx.x;
    if (e >= E) return;
    int s = edge_at(eidx, e);
    int d = edge_at(eidx, (long long)E + e);
    int pos = atomicAdd(&g_cur[d], 1);
    g_nbr[pos] = s;
}

// ---------------------------------------------------------------------------
// Aggregation: one warp per node. z = (1+eps)*h[i] + sum_nbr h[j] -> fp16 hi/lo
// ---------------------------------------------------------------------------
__device__ __forceinline__ uint32_t pack_h2(__half x, __half y) {
    __half2 p = __halves2half2(x, y);
    return *reinterpret_cast<uint32_t*>(&p);
}

__global__ void agg_kernel(const float* __restrict__ h,
                           __half* __restrict__ zhi,
                           __half* __restrict__ zlo,
                           const float* __restrict__ eps, int M) {
    int warp = (blockIdx.x * blockDim.x + threadIdx.x) >> 5;
    int lane = threadIdx.x & 31;
    if (warp >= M) return;
    const float4* hp = (const float4*)h;

    float4 acc = hp[(size_t)warp * 32 + lane];
    float se = 1.0f + __ldg(eps);
    acc.x *= se; acc.y *= se; acc.z *= se; acc.w *= se;

    int p   = g_off[warp];
    int end = p + g_deg[warp];
    for (; p + 4 <= end; p += 4) {
        int j0 = g_nbr[p], j1 = g_nbr[p + 1], j2 = g_nbr[p + 2], j3 = g_nbr[p + 3];
        float4 v0 = hp[(size_t)j0 * 32 + lane];
        float4 v1 = hp[(size_t)j1 * 32 + lane];
        float4 v2 = hp[(size_t)j2 * 32 + lane];
        float4 v3 = hp[(size_t)j3 * 32 + lane];
        acc.x += v0.x + v1.x + v2.x + v3.x;
        acc.y += v0.y + v1.y + v2.y + v3.y;
        acc.z += v0.z + v1.z + v2.z + v3.z;
        acc.w += v0.w + v1.w + v2.w + v3.w;
    }
    for (; p < end; p++) {
        float4 v = hp[(size_t)g_nbr[p] * 32 + lane];
        acc.x += v.x; acc.y += v.y; acc.z += v.z; acc.w += v.w;
    }

    __half h0 = __float2half_rn(acc.x), h1 = __float2half_rn(acc.y);
    __half h2 = __float2half_rn(acc.z), h3 = __float2half_rn(acc.w);
    __half l0 = __float2half_rn(acc.x - __half2float(h0));
    __half l1 = __float2half_rn(acc.y - __half2float(h1));
    __half l2 = __float2half_rn(acc.z - __half2float(h2));
    __half l3 = __float2half_rn(acc.w - __half2float(h3));
    size_t o = (size_t)warp * 128 + lane * 4;
    *(uint2*)&zhi[o] = make_uint2(pack_h2(h0, h1), pack_h2(h2, h3));
    *(uint2*)&zlo[o] = make_uint2(pack_h2(l0, l1), pack_h2(l2, l3));
}

// ---------------------------------------------------------------------------
// Weight prep (all 7): W[K][N] fp32 -> transposed fp16 [N][K]  (hi only)
// ---------------------------------------------------------------------------
struct WSeg { const float* src; int K, N, off; };
struct WAll { WSeg s[7]; };

__global__ void wprep_all(WAll wa, __half* __restrict__ hi) {
    int i = blockIdx.x * blockDim.x + threadIdx.x;
    #pragma unroll
    for (int j = 0; j < 7; j++) {
        WSeg sg = wa.s[j];
        int loc = i - sg.off;
        if (loc >= 0 && loc < sg.K * sg.N) {
            int k = loc / sg.N, n = loc % sg.N;
            hi[sg.off + n * sg.K + k] = __float2half_rn(sg.src[loc]);
        }
    }
}

// x [M,64] fp32 -> split fp16
__global__ void xprep_kernel(const float* __restrict__ x,
                             __half* __restrict__ hi,
                             __half* __restrict__ lo, int n) {
    int i = blockIdx.x * blockDim.x + threadIdx.x;
    if (i >= n) return;
    float v = x[i];
    __half h = __float2half_rn(v);
    hi[i] = h;
    lo[i] = __float2half_rn(v - __half2float(h));
}

// ---------------------------------------------------------------------------
// MMA helpers (fp16)
// ---------------------------------------------------------------------------
__device__ __forceinline__ void mma_f16(float c[4], const uint32_t a[4],
                                        uint32_t b0, uint32_t b1) {
    asm volatile(
        "mma.sync.aligned.m16n8k16.row.col.f32.f16.f16.f32 "
        "{%0,%1,%2,%3}, {%4,%5,%6,%7}, {%8,%9}, {%0,%1,%2,%3};"
        : "+f"(c[0]), "+f"(c[1]), "+f"(c[2]), "+f"(c[3])
        : "r"(a[0]), "r"(a[1]), "r"(a[2]), "r"(a[3]), "r"(b0), "r"(b1));
}

__device__ __forceinline__ void ldsm_x4(uint32_t r[4], uint32_t saddr) {
    asm volatile("ldmatrix.sync.aligned.m8n8.x4.shared.b16 {%0,%1,%2,%3}, [%4];"
                 : "=r"(r[0]), "=r"(r[1]), "=r"(r[2]), "=r"(r[3])
                 : "r"(saddr));
}

__device__ __forceinline__ void cp16(uint32_t saddr, const void* gaddr) {
    asm volatile("cp.async.ca.shared.global [%0], [%1], 16;"
                 :: "r"(saddr), "l"(gaddr) : "memory");
}

// ---------------------------------------------------------------------------
// 2-term fp16 tensor-core GEMM: C = act((Ah+Al) @ Wh + bias)
// CTA tile 128x128, BK=32, 8 warps (4x2), warp 32x64.
// Dynamic smem: 2 stages x {Ah, Al, Bh} x 128x40 half = 2 x 30720 B.
// ---------------------------------------------------------------------------
#define STG_ELEM  5120                    // 128*40 halves per array
#define STG_BYTES (3 * STG_ELEM * 2)      // 30720 bytes per stage

template <int K, int NTOT, bool RELU, bool SPLITOUT>
__global__ __launch_bounds__(256, 2) void mma_gemm(
    const __half* __restrict__ Ahi_g,
    const __half* __restrict__ Alo_g,
    const __half* __restrict__ Wh,
    const float* __restrict__ bias,
    float* __restrict__ C,
    __half* __restrict__ Chi,
    __half* __restrict__ Clo,
    int M) {

    extern __shared__ __half smem[];
    const uint32_t sbase = (uint32_t)__cvta_generic_to_shared(smem);

    const int tid  = threadIdx.x;
    const int lane = tid & 31;
    const int warp = tid >> 5;
    const int wm   = warp >> 1;
    const int wn   = warp & 1;
    const int m0   = blockIdx.x * 128;
    const int n0   = blockIdx.y * 128;
    const int g    = lane >> 2;
    const int q4   = lane & 3;

    const int arow = (lane & 7) + ((lane >> 3) & 1) * 8;
    const int akq  = (lane >> 4) * 8;
    const int bn   = (lane & 7) + ((lane >> 4) & 1) * 8;
    const int bkq  = ((lane >> 3) & 1) * 8;

    uint32_t aBase[2], bBase[4];
    #pragma unroll
    for (int mt = 0; mt < 2; mt++) {
        int r = wm * 32 + mt * 16 + arow;
        aBase[mt] = sbase + (uint32_t)(r * 40 + akq) * 2;
    }
    #pragma unroll
    for (int ntp = 0; ntp < 4; ntp++) {
        int n = wn * 64 + ntp * 16 + bn;
        bBase[ntp] = sbase + (uint32_t)(2 * STG_ELEM + n * 40 + bkq) * 2;
    }

    auto issue_tile = [&](int s, int k0) {
        uint32_t b = sbase + (uint32_t)s * STG_BYTES;
        #pragma unroll
        for (int rep = 0; rep < 2; rep++) {
            int i = tid + rep * 256;
            int row = i >> 2, q = i & 3;
            uint32_t so = (uint32_t)(row * 40 + q * 8) * 2;
            size_t ga = (size_t)(m0 + row) * K + k0 + q * 8;
            size_t gb = (size_t)(n0 + row) * K + k0 + q * 8;
            cp16(b + so, Ahi_g + ga);
            cp16(b + STG_ELEM * 2 + so, Alo_g + ga);
            cp16(b + 2 * STG_ELEM * 2 + so, Wh + gb);
        }
        asm volatile("cp.async.commit_group;");
    };

    float acc[2][8][4];
    #pragma unroll
    for (int mt = 0; mt < 2; mt++)
        #pragma unroll
        for (int nt = 0; nt < 8; nt++)
            #pragma unroll
            for (int j = 0; j < 4; j++) acc[mt][nt][j] = 0.0f;

    constexpr int NIT = K / 32;
    issue_tile(0, 0);

    #pragma unroll
    for (int it = 0; it < NIT; it++) {
        if (it + 1 < NIT) {
            issue_tile((it + 1) & 1, (it + 1) * 32);
            asm volatile("cp.async.wait_group 1;");
        } else {
            asm volatile("cp.async.wait_group 0;");
        }
        __syncthreads();

        const uint32_t st = (uint32_t)(it & 1) * STG_BYTES;
        #pragma unroll
        for (int ks = 0; ks < 32; ks += 16) {
            const uint32_t kofs = st + (uint32_t)ks * 2;
            uint32_t ah[2][4], al[2][4];
            #pragma unroll
            for (int mt = 0; mt < 2; mt++) {
                ldsm_x4(ah[mt], aBase[mt] + kofs);
                ldsm_x4(al[mt], aBase[mt] + STG_ELEM * 2 + kofs);
            }
            uint32_t bh[4][4];
            #pragma unroll
            for (int ntp = 0; ntp < 4; ntp++)
                ldsm_x4(bh[ntp], bBase[ntp] + kofs);
            #pragma unroll
            for (int nt = 0; nt < 8; nt++) {
                uint32_t b0 = bh[nt >> 1][(nt & 1) * 2];
                uint32_t b1 = bh[nt >> 1][(nt & 1) * 2 + 1];
                #pragma unroll
                for (int mt = 0; mt < 2; mt++) {
                    mma_f16(acc[mt][nt], ah[mt], b0, b1);
                    mma_f16(acc[mt][nt], al[mt], b0, b1);
                }
            }
        }
        __syncthreads();
    }

    // ---- epilogue ----
    #pragma unroll
    for (int mt = 0; mt < 2; mt++) {
        #pragma unroll
        for (int nt = 0; nt < 8; nt++) {
            int c = n0 + wn * 64 + nt * 8 + 2 * q4;
            float2 bv = make_float2(0.f, 0.f);
            if (bias) bv = *(const float2*)&bias[c];
            int r = m0 + wm * 32 + mt * 16 + g;
            float2 o0, o1;
            o0.x = acc[mt][nt][0] + bv.x;
            o0.y = acc[mt][nt][1] + bv.y;
            o1.x = acc[mt][nt][2] + bv.x;
            o1.y = acc[mt][nt][3] + bv.y;
            if (RELU) {
                o0.x = fmaxf(o0.x, 0.f); o0.y = fmaxf(o0.y, 0.f);
                o1.x = fmaxf(o1.x, 0.f); o1.y = fmaxf(o1.y, 0.f);
            }
            #pragma unroll
            for (int half = 0; half < 2; half++) {
                int rr = r + half * 8;
                float2 o = half ? o1 : o0;
                if (rr < M) {
                    if (SPLITOUT) {
                        __half hx = __float2half_rn(o.x);
                        __half hy = __float2half_rn(o.y);
                        __half lx = __float2half_rn(o.x - __half2float(hx));
                        __half ly = __float2half_rn(o.y - __half2float(hy));
                        *(uint32_t*)&Chi[(size_t)rr * NTOT + c] = pack_h2(hx, hy);
                        *(uint32_t*)&Clo[(size_t)rr * NTOT + c] = pack_h2(lx, ly);
                    } else {
                        *(float2*)&C[(size_t)rr * NTOT + c] = o;
                    }
                }
            }
        }
    }
}

// ---------------------------------------------------------------------------
// Host side
// ---------------------------------------------------------------------------
static __half* s_whi;

template <int K, int NTOT, bool RELU, bool SPLITOUT>
static void run_gemm(const __half* Ahi, const __half* Alo,
                     int woff, const float* bias,
                     float* C, __half* Chi, __half* Clo, int M) {
    cudaFuncSetAttribute(mma_gemm<K, NTOT, RELU, SPLITOUT>,
                         cudaFuncAttributeMaxDynamicSharedMemorySize,
                         2 * STG_BYTES);
    dim3 grid((M + 127) / 128, NTOT / 128);
    mma_gemm<K, NTOT, RELU, SPLITOUT><<<grid, 256, 2 * STG_BYTES>>>(
        Ahi, Alo, s_whi + woff, bias, C, Chi, Clo, M);
}

extern "C" void kernel_launch(void* const* d_in, const int* in_sizes, int n_in,
                              void* d_out, int out_size) {
    const float* x       = (const float*)d_in[0];
    const void*  eidx    = d_in[1];
    const float* W_embed = (const float*)d_in[2];
    const float* eps1    = (const float*)d_in[3];
    const float* w1a     = (const float*)d_in[4];
    const float* b1a     = (const float*)d_in[5];
    const float* w1b     = (const float*)d_in[6];
    const float* b1b     = (const float*)d_in[7];
    const float* eps2    = (const float*)d_in[8];
    const float* w2a     = (const float*)d_in[9];
    const float* b2a     = (const float*)d_in[10];
    const float* w2b     = (const float*)d_in[11];
    const float* b2b     = (const float*)d_in[12];
    const float* eps3    = (const float*)d_in[13];
    const float* w3a     = (const float*)d_in[14];
    const float* b3a     = (const float*)d_in[15];
    const float* w3b     = (const float*)d_in[16];
    const float* b3b     = (const float*)d_in[17];

    const int M = in_sizes[0] / 64;
    const int E = in_sizes[1] / 2;

    float* ph;
    __half *pzhi, *pzlo, *pthi, *ptlo;
    int *pdeg, *palloc;
    cudaGetSymbolAddress((void**)&ph,   g_h);
    cudaGetSymbolAddress((void**)&pzhi, g_zhi);
    cudaGetSymbolAddress((void**)&pzlo, g_zlo);
    cudaGetSymbolAddress((void**)&pthi, g_thi);
    cudaGetSymbolAddress((void**)&ptlo, g_tlo);
    cudaGetSymbolAddress((void**)&s_whi, g_whi);
    cudaGetSymbolAddress((void**)&pdeg, g_deg);
    cudaGetSymbolAddress((void**)&palloc, g_alloc);
    float* out = (float*)d_out;

    const int eBlks   = (E + 255) / 256;
    const int aggBlks = (M + 7) / 8;

    static cudaStream_t s1 = nullptr;
    static cudaEvent_t evFork = nullptr, evJoin = nullptr;
    if (!s1) {
        cudaStreamCreateWithFlags(&s1, cudaStreamNonBlocking);
        cudaEventCreateWithFlags(&evFork, cudaEventDisableTiming);
        cudaEventCreateWithFlags(&evJoin, cudaEventDisableTiming);
    }

    // ---- fork: CSR build on s1 ----
    cudaEventRecord(evFork, 0);
    cudaStreamWaitEvent(s1, evFork, 0);

    cudaMemsetAsync(pdeg, 0, (size_t)M * sizeof(int), s1);
    cudaMemsetAsync(palloc, 0, sizeof(int), s1);
    detect_kernel<<<1, 1, 0, s1>>>((const int*)eidx);
    hist_kernel<<<eBlks, 256, 0, s1>>>(eidx, E);
    offsets_kernel<<<(M + 255) / 256, 256, 0, s1>>>(M);
    fill_kernel<<<eBlks, 256, 0, s1>>>(eidx, E);
    cudaEventRecord(evJoin, s1);

    // ---- main stream: weights + x split + embed ----
    WAll wa;
    wa.s[0] = {W_embed,  64, 128, 0};
    wa.s[1] = {w1a, 128, 128, 8192};
    wa.s[2] = {w1b, 128, 128, 24576};
    wa.s[3] = {w2a, 128, 256, 40960};
    wa.s[4] = {w2b, 256, 128, 73728};
    wa.s[5] = {w3a, 128, 256, 106496};
    wa.s[6] = {w3b, 256, 128, 139264};
    wprep_all<<<(WTOTAL + 255) / 256, 256>>>(wa, s_whi);

    xprep_kernel<<<(M * 64 + 255) / 256, 256>>>(x, pthi, ptlo, M * 64);

    // embed: h = x @ W_embed
    run_gemm<64, 128, false, false>(pthi, ptlo, 0, nullptr,
                                    ph, nullptr, nullptr, M);

    cudaStreamWaitEvent(0, evJoin, 0);

    // ---- conv1 ----
    agg_kernel<<<aggBlks, 256>>>(ph, pzhi, pzlo, eps1, M);
    run_gemm<128, 128, true,  true >(pzhi, pzlo, 8192,  b1a,
                                     nullptr, pthi, ptlo, M);
    run_gemm<128, 128, false, false>(pthi, ptlo, 24576, b1b,
                                     ph, nullptr, nullptr, M);

    // ---- conv2 ----
    agg_kernel<<<aggBlks, 256>>>(ph, pzhi, pzlo, eps2, M);
    run_gemm<128, 256, true, true >(pzhi, pzlo, 40960, b2a,
                                    nullptr, pthi, ptlo, M);
    run_gemm<256, 128, true, false>(pthi, ptlo, 73728, b2b,
                                    ph, nullptr, nullptr, M);

    // ---- conv3 ----
    agg_kernel<<<aggBlks, 256>>>(ph, pzhi, pzlo, eps3, M);
    run_gemm<128, 256, true, true >(pzhi, pzlo, 106496, b3a,
                                    nullptr, pthi, ptlo, M);
    run_gemm<256, 128, true, false>(pthi, ptlo, 139264, b3b,
                                    out, nullptr, nullptr, M);
}